// round 6
// baseline (speedup 1.0000x reference)
#include <cuda_runtime.h>
#include <cuda_bf16.h>
#include <cstdint>

#define NN 8192
#define DD 128
#define KNN 20
#define NC 10
#define NW 256    // 32-bit words per mask row
#define HB 2048   // histogram bins
#define BCAP 256  // boundary candidate capacity
#define KC 32     // K-chunk for dist tiles
#define TSTR 40   // smem tile row stride in bf16 (conflict-free)
#define TILE (128 * TSTR)                 // elems per tile array
#define STAGE_E (4 * TILE)                // elems per stage (Ahi,Alo,Bhi,Blo)
#define DIST_SMEM (2 * STAGE_E * 2)       // bytes (2 stages, bf16)

// ---------------- scratch (device globals; no allocations) ----------------
__device__ float          g_dist[(size_t)NN * NN];
__device__ float          g_sq[NN];
__device__ float          g_density[NN];
__device__ unsigned int   g_mask[(size_t)NN * NW];
__device__ __nv_bfloat16  g_Xhi[(size_t)NN * DD];
__device__ __nv_bfloat16  g_Xlo[(size_t)NN * DD];

// ---------------- kernel 1: zero the mask ----------------
__global__ void zero_mask_kernel() {
    int i = blockIdx.x * blockDim.x + threadIdx.x;
    if (i < NN * NW) g_mask[i] = 0u;
}

// ---------------- kernel 2: split X -> bf16 hi/lo + row norms -------------
__global__ void prep_kernel(const float* __restrict__ X) {
    int row  = blockIdx.x * 8 + (threadIdx.x >> 5);
    int lane = threadIdx.x & 31;
    float4 v = ((const float4*)(X + (size_t)row * DD))[lane];

    __nv_bfloat16 h0 = __float2bfloat16(v.x);
    __nv_bfloat16 h1 = __float2bfloat16(v.y);
    __nv_bfloat16 h2 = __float2bfloat16(v.z);
    __nv_bfloat16 h3 = __float2bfloat16(v.w);
    __nv_bfloat16 l0 = __float2bfloat16(v.x - __bfloat162float(h0));
    __nv_bfloat16 l1 = __float2bfloat16(v.y - __bfloat162float(h1));
    __nv_bfloat16 l2 = __float2bfloat16(v.z - __bfloat162float(h2));
    __nv_bfloat16 l3 = __float2bfloat16(v.w - __bfloat162float(h3));

    uint2 ph, pl;
    ph.x = ((unsigned)__bfloat16_as_ushort(h1) << 16) | __bfloat16_as_ushort(h0);
    ph.y = ((unsigned)__bfloat16_as_ushort(h3) << 16) | __bfloat16_as_ushort(h2);
    pl.x = ((unsigned)__bfloat16_as_ushort(l1) << 16) | __bfloat16_as_ushort(l0);
    pl.y = ((unsigned)__bfloat16_as_ushort(l3) << 16) | __bfloat16_as_ushort(l2);
    ((uint2*)g_Xhi)[(size_t)row * 32 + lane] = ph;
    ((uint2*)g_Xlo)[(size_t)row * 32 + lane] = pl;

    float s = v.x * v.x + v.y * v.y + v.z * v.z + v.w * v.w;
#pragma unroll
    for (int o = 16; o; o >>= 1) s += __shfl_xor_sync(0xffffffffu, s, o);
    if (lane == 0) g_sq[row] = s;
}

// ---------------- ptx helpers ----------------
__device__ __forceinline__ void mma_bf16(float* c, const unsigned* a,
                                         unsigned b0, unsigned b1) {
    asm volatile(
        "mma.sync.aligned.m16n8k16.row.col.f32.bf16.bf16.f32 "
        "{%0,%1,%2,%3}, {%4,%5,%6,%7}, {%8,%9}, {%0,%1,%2,%3};"
        : "+f"(c[0]), "+f"(c[1]), "+f"(c[2]), "+f"(c[3])
        : "r"(a[0]), "r"(a[1]), "r"(a[2]), "r"(a[3]), "r"(b0), "r"(b1));
}
__device__ __forceinline__ void ldsm_x4(unsigned* r, unsigned addr) {
    asm volatile("ldmatrix.sync.aligned.m8n8.x4.shared.b16 {%0,%1,%2,%3}, [%4];"
                 : "=r"(r[0]), "=r"(r[1]), "=r"(r[2]), "=r"(r[3]) : "r"(addr));
}
__device__ __forceinline__ void ldsm_x2(unsigned& r0, unsigned& r1, unsigned addr) {
    asm volatile("ldmatrix.sync.aligned.m8n8.x2.shared.b16 {%0,%1}, [%2];"
                 : "=r"(r0), "=r"(r1) : "r"(addr));
}
__device__ __forceinline__ void cp16(unsigned dst, const void* src) {
    asm volatile("cp.async.cg.shared.global [%0], [%1], 16;" :: "r"(dst), "l"(src));
}
__device__ __forceinline__ void cp_commit() {
    asm volatile("cp.async.commit_group;");
}
__device__ __forceinline__ void cp_wait0() {
    asm volatile("cp.async.wait_group 0;");
}

// ---------------- kernel 3: tensor-core squared-distance matrix -----------
// 128x128 block tile, 8 warps (4x2), warp = 32(M)x64(N). Split-bf16
// (hi.hi + hi.lo + lo.hi, fp32 accum). ldmatrix operand loads, cp.async
// double-buffered K-chunks.
__global__ __launch_bounds__(256, 2) void dist_tc_kernel() {
    extern __shared__ __align__(16) __nv_bfloat16 dsm[];
    unsigned sbase = (unsigned)__cvta_generic_to_shared(dsm);

    int bi = blockIdx.y, bj = blockIdx.x;
    int row0 = bi * 128, col0 = bj * 128;

    int tid  = threadIdx.x;
    int w    = tid >> 5, lane = tid & 31;
    int wm   = w & 3,    wn   = w >> 2;
    int g    = lane >> 2, tig = lane & 3;

    float C[2][8][4];
#pragma unroll
    for (int mt = 0; mt < 2; mt++)
#pragma unroll
        for (int nt = 0; nt < 8; nt++)
#pragma unroll
            for (int q = 0; q < 4; q++) C[mt][nt][q] = 0.f;

    // loader lambda-ish: stage s, chunk kb
    int lr  = tid >> 2;           // 0..63 -> covers rows in 2 passes
    int lc8 = (tid & 3) * 8;      // k offset within chunk (8 bf16 = 16 B)

#pragma unroll 1
    for (int pre = 0; pre < 1; pre++) {   // issue stage 0 loads
#pragma unroll
        for (int u = 0; u < 2; u++) {
            int r = lr + u * 64;
            unsigned db = sbase + (unsigned)((r * TSTR + lc8) * 2);
            size_t goA = (size_t)(row0 + r) * DD + lc8;
            size_t goB = (size_t)(col0 + r) * DD + lc8;
            cp16(db + 0 * TILE * 2, &g_Xhi[goA]);
            cp16(db + 1 * TILE * 2, &g_Xlo[goA]);
            cp16(db + 2 * TILE * 2, &g_Xhi[goB]);
            cp16(db + 3 * TILE * 2, &g_Xlo[goB]);
        }
        cp_commit();
    }

#pragma unroll
    for (int kb = 0; kb < DD / KC; kb++) {
        cp_wait0();
        __syncthreads();

        if (kb < DD / KC - 1) {   // issue next chunk into other stage
            unsigned soff = (unsigned)(((kb + 1) & 1) * STAGE_E * 2);
            int kn = (kb + 1) * KC;
#pragma unroll
            for (int u = 0; u < 2; u++) {
                int r = lr + u * 64;
                unsigned db = sbase + soff + (unsigned)((r * TSTR + lc8) * 2);
                size_t goA = (size_t)(row0 + r) * DD + kn + lc8;
                size_t goB = (size_t)(col0 + r) * DD + kn + lc8;
                cp16(db + 0 * TILE * 2, &g_Xhi[goA]);
                cp16(db + 1 * TILE * 2, &g_Xlo[goA]);
                cp16(db + 2 * TILE * 2, &g_Xhi[goB]);
                cp16(db + 3 * TILE * 2, &g_Xlo[goB]);
            }
            cp_commit();
        }

        unsigned sb = sbase + (unsigned)((kb & 1) * STAGE_E * 2);
#pragma unroll
        for (int ks = 0; ks < KC; ks += 16) {
            unsigned ahi[2][4], alo[2][4];
            int arow = (lane & 15);
            int akc  = ks + (lane >> 4) * 8;
#pragma unroll
            for (int mt = 0; mt < 2; mt++) {
                int row = wm * 32 + mt * 16 + arow;
                unsigned ao = sb + (unsigned)((row * TSTR + akc) * 2);
                ldsm_x4(ahi[mt], ao + 0 * TILE * 2);
                ldsm_x4(alo[mt], ao + 1 * TILE * 2);
            }
            int brow = (lane & 7);
            int bkc  = ks + ((lane >> 3) & 1) * 8;
#pragma unroll
            for (int nt = 0; nt < 8; nt++) {
                int n = wn * 64 + nt * 8 + brow;
                unsigned bo = sb + (unsigned)((n * TSTR + bkc) * 2);
                unsigned bh0, bh1, bl0, bl1;
                ldsm_x2(bh0, bh1, bo + 2 * TILE * 2);
                ldsm_x2(bl0, bl1, bo + 3 * TILE * 2);
#pragma unroll
                for (int mt = 0; mt < 2; mt++) {
                    mma_bf16(C[mt][nt], ahi[mt], bh0, bh1);
                    mma_bf16(C[mt][nt], ahi[mt], bl0, bl1);
                    mma_bf16(C[mt][nt], alo[mt], bh0, bh1);
                }
            }
        }
        __syncthreads();
    }

    // epilogue: d2 = sa + sb - 2*dot, clamped
    float sb0[8], sb1[8];
#pragma unroll
    for (int nt = 0; nt < 8; nt++) {
        int n = col0 + wn * 64 + nt * 8 + tig * 2;
        sb0[nt] = g_sq[n];
        sb1[nt] = g_sq[n + 1];
    }
#pragma unroll
    for (int mt = 0; mt < 2; mt++) {
        int m0 = row0 + wm * 32 + mt * 16;
        float saA = g_sq[m0 + g];
        float saB = g_sq[m0 + g + 8];
#pragma unroll
        for (int nt = 0; nt < 8; nt++) {
            int n = col0 + wn * 64 + nt * 8 + tig * 2;
            float2 oA, oB;
            oA.x = fmaxf(saA + sb0[nt] - 2.f * C[mt][nt][0], 0.f);
            oA.y = fmaxf(saA + sb1[nt] - 2.f * C[mt][nt][1], 0.f);
            oB.x = fmaxf(saB + sb0[nt] - 2.f * C[mt][nt][2], 0.f);
            oB.y = fmaxf(saB + sb1[nt] - 2.f * C[mt][nt][3], 0.f);
            *(float2*)(g_dist + (size_t)(m0 + g) * NN + n)     = oA;
            *(float2*)(g_dist + (size_t)(m0 + g + 8) * NN + n) = oB;
        }
    }
}

// ---------------- kernel 4: per-row top-K, histogram select ---------------
// Per-warp private u16 histograms (match_any leader updates, NO atomics in
// the histogram pass). Pass 2 re-reads the row from L2.
__global__ __launch_bounds__(256) void topk_kernel() {
    int i = blockIdx.x, tid = threadIdx.x;
    int lane = tid & 31, wid = tid >> 5;

    __shared__ unsigned short whist[8][HB];           // 32 KB
    __shared__ unsigned long long bnd[BCAP];          // 2 KB
    __shared__ unsigned long long cand[32];
    __shared__ int wsum[8];
    __shared__ int s_pivot, s_below, n_cand, n_bnd;

    for (int j = tid; j < 8 * HB / 2; j += 256) ((unsigned*)whist)[j] = 0u;
    if (tid == 0) { n_cand = 0; n_bnd = 0; }
    __syncthreads();

    const float4* r4 = (const float4*)(g_dist + (size_t)i * NN);
    unsigned short* mh = whist[wid];

    // pass 1: private per-warp histogram of float bits >> 20
#pragma unroll
    for (int u = 0; u < 8; u++) {
        float4 v = r4[tid + 256 * u];
        float e[4] = {v.x, v.y, v.z, v.w};
#pragma unroll
        for (int q = 0; q < 4; q++) {
            unsigned bin = __float_as_uint(e[q]) >> 20;
            unsigned peers = __match_any_sync(0xffffffffu, bin);
            if (lane == __ffs(peers) - 1)
                mh[bin] = (unsigned short)(mh[bin] + __popc(peers));
        }
    }
    __syncthreads();

    // block prefix scan over per-thread partials (8 bins each, summed
    // across the 8 warp-private histograms) -> pivot bin
    int hsum[8];
    int p = 0;
#pragma unroll
    for (int q = 0; q < 8; q++) {
        int h = 0;
#pragma unroll
        for (int ww = 0; ww < 8; ww++) h += whist[ww][tid * 8 + q];
        hsum[q] = h;
        p += h;
    }
    int v = p;
#pragma unroll
    for (int o = 1; o < 32; o <<= 1) {
        int n = __shfl_up_sync(0xffffffffu, v, o);
        if (lane >= o) v += n;
    }
    if (lane == 31) wsum[wid] = v;
    __syncthreads();
    if (tid < 8) {
        int w = wsum[tid];
#pragma unroll
        for (int o = 1; o < 8; o <<= 1) {
            int n = __shfl_up_sync(0xffu, w, o);
            if (tid >= o) w += n;
        }
        wsum[tid] = w;
    }
    __syncthreads();
    int incl = v + (wid ? wsum[wid - 1] : 0);
    int excl = incl - p;
    if (excl < KNN && incl >= KNN) {
        int c = excl, B = 0;
        for (int q = 0; q < 8; q++) {
            if (c + hsum[q] >= KNN) { B = tid * 8 + q; break; }
            c += hsum[q];
        }
        s_pivot = B;
        s_below = c;
    }
    __syncthreads();

    // pass 2 (L2-hot): collect below-pivot + boundary-bin candidates
    unsigned B = (unsigned)s_pivot;
#pragma unroll
    for (int u = 0; u < 8; u++) {
        int j4 = tid + 256 * u;
        float4 vv = r4[j4];
        float elem[4] = {vv.x, vv.y, vv.z, vv.w};
#pragma unroll
        for (int q = 0; q < 4; q++) {
            unsigned bb = __float_as_uint(elem[q]);
            unsigned bin = bb >> 20;
            if (bin <= B) {
                int j = j4 * 4 + q;
                unsigned long long key =
                    ((unsigned long long)bb << 32) | (unsigned)j;
                if (bin < B) {
                    cand[atomicAdd(&n_cand, 1)] = key;     // guaranteed < 20
                } else {
                    int pos = atomicAdd(&n_bnd, 1);
                    if (pos < BCAP) bnd[pos] = key;
                }
            }
        }
    }
    __syncthreads();

    // warp 0: exact selection from boundary bin + finish row
    if (wid == 0) {
        int below = s_below;
        int need  = KNN - below;
        int nb    = n_bnd;
        if (nb <= BCAP) {
            for (int t = 0; t < need; t++) {
                unsigned long long m = 0xFFFFFFFFFFFFFFFFull;
                for (int j = lane; j < nb; j += 32) {
                    unsigned long long k = bnd[j];
                    if (k < m) m = k;
                }
#pragma unroll
                for (int o = 16; o; o >>= 1) {
                    unsigned long long oth = __shfl_xor_sync(0xffffffffu, m, o);
                    if (oth < m) m = oth;
                }
                for (int j = lane; j < nb; j += 32)
                    if (bnd[j] == m) bnd[j] = 0xFFFFFFFFFFFFFFFFull;
                if (lane == 0) cand[below + t] = m;
            }
        } else {
            const float* row = g_dist + (size_t)i * NN;
            unsigned long long last = 0;
            for (int t = 0; t < need; t++) {
                unsigned long long m = 0xFFFFFFFFFFFFFFFFull;
                for (int j = lane; j < NN; j += 32) {
                    unsigned bb = __float_as_uint(row[j]);
                    if ((bb >> 20) == B) {
                        unsigned long long key =
                            ((unsigned long long)bb << 32) | (unsigned)j;
                        if ((t == 0 || key > last) && key < m) m = key;
                    }
                }
#pragma unroll
                for (int o = 16; o; o >>= 1) {
                    unsigned long long oth = __shfl_xor_sync(0xffffffffu, m, o);
                    if (oth < m) m = oth;
                }
                last = m;
                if (lane == 0) cand[below + t] = m;
            }
        }
        __syncwarp();

        float d = 0.f;
        if (lane < KNN) {
            unsigned long long k = cand[lane];
            int idx = (int)(k & 0xFFFFFFFFull);
            d = sqrtf(__uint_as_float((unsigned)(k >> 32)));
            atomicOr(&g_mask[(size_t)i * NW + (idx >> 5)], 1u << (idx & 31));
            atomicOr(&g_mask[(size_t)idx * NW + (i >> 5)], 1u << (i & 31));
        }
#pragma unroll
        for (int o = 16; o; o >>= 1) d += __shfl_xor_sync(0xffffffffu, d, o);
        if (lane == 0)
            g_density[i] = 1.0f / (d / (float)KNN + 1e-10f);
    }
}

// ---------------- kernel 5: influence average + score + classify ----------
__global__ void final_kernel(const float* __restrict__ logits,
                             float* __restrict__ out, int out_size) {
    int row  = blockIdx.x * 8 + (threadIdx.x >> 5);
    int lane = threadIdx.x & 31;
    const unsigned int* mr = g_mask + (size_t)row * NW;

    float s = 0.f;
    int cnt = 0;
#pragma unroll
    for (int u = 0; u < 8; u++) {
        int w = lane + 32 * u;
        unsigned int bits = mr[w];
        cnt += __popc(bits);
        while (bits) {
            int b = __ffs(bits) - 1;
            bits &= bits - 1;
            s += g_density[w * 32 + b];
        }
    }
#pragma unroll
    for (int o = 16; o; o >>= 1) {
        s   += __shfl_xor_sync(0xffffffffu, s, o);
        cnt += __shfl_xor_sync(0xffffffffu, cnt, o);
    }
    if (lane == 0) {
        float den   = g_density[row];
        float avg   = s / (float)(cnt > 0 ? cnt : 1);
        float score = -(den / (avg + 1e-10f));
        out[row] = score;
        bool flag = score < -0.5f;
        if (out_size >= 2 * NN) out[NN + row] = flag ? 1.f : 0.f;
        if (out_size >= 3 * NN) {
            int pred = -1;
            if (!flag) {
                const float* lg = logits + (size_t)row * NC;
                float best = lg[0]; pred = 0;
#pragma unroll
                for (int c = 1; c < NC; c++)
                    if (lg[c] > best) { best = lg[c]; pred = c; }
            }
            out[2 * NN + row] = (float)pred;
        }
    }
}

// ---------------- launch ----------------
extern "C" void kernel_launch(void* const* d_in, const int* in_sizes, int n_in,
                              void* d_out, int out_size) {
    (void)in_sizes; (void)n_in;
    const float* X = (const float*)d_in[0];   // embeddings [8192,128] f32
    const float* L = (const float*)d_in[1];   // logits     [8192,10]  f32
    float* out = (float*)d_out;

    static int smem_set = 0;
    if (!smem_set) {
        cudaFuncSetAttribute(dist_tc_kernel,
                             cudaFuncAttributeMaxDynamicSharedMemorySize,
                             DIST_SMEM);
        smem_set = 1;
    }

    zero_mask_kernel<<<(NN * NW + 255) / 256, 256>>>();
    prep_kernel<<<NN / 8, 256>>>(X);
    dim3 g(NN / 128, NN / 128);
    dist_tc_kernel<<<g, 256, DIST_SMEM>>>();
    topk_kernel<<<NN, 256>>>();
    final_kernel<<<NN / 8, 256>>>(L, out, out_size);
}

// round 7
// speedup vs baseline: 1.0302x; 1.0302x over previous
#include <cuda_runtime.h>
#include <cuda_bf16.h>
#include <cstdint>

#define NN 8192
#define DD 128
#define KNN 20
#define NC 10
#define NW 256    // 32-bit words per mask row
#define HB 2048   // histogram bins
#define BCAP 256  // boundary candidate capacity
#define KC 32     // K-chunk for dist tiles
#define TSTR 40   // smem tile row stride in bf16 (conflict-free)
#define TILE (128 * TSTR)                 // elems per tile array
#define STAGE_E (4 * TILE)                // elems per stage (Ahi,Alo,Bhi,Blo)
#define DIST_SMEM (2 * STAGE_E * 2)       // bytes (2 stages, bf16)

// ---------------- scratch (device globals; no allocations) ----------------
__device__ float          g_dist[(size_t)NN * NN];
__device__ float          g_sq[NN];
__device__ float          g_density[NN];
__device__ unsigned int   g_mask[(size_t)NN * NW];
__device__ __nv_bfloat16  g_Xhi[(size_t)NN * DD];
__device__ __nv_bfloat16  g_Xlo[(size_t)NN * DD];

// ---------------- kernel 1: zero the mask ----------------
__global__ void zero_mask_kernel() {
    int i = blockIdx.x * blockDim.x + threadIdx.x;
    if (i < NN * NW) g_mask[i] = 0u;
}

// ---------------- kernel 2: split X -> bf16 hi/lo + row norms -------------
__global__ void prep_kernel(const float* __restrict__ X) {
    int row  = blockIdx.x * 8 + (threadIdx.x >> 5);
    int lane = threadIdx.x & 31;
    float4 v = ((const float4*)(X + (size_t)row * DD))[lane];

    __nv_bfloat16 h0 = __float2bfloat16(v.x);
    __nv_bfloat16 h1 = __float2bfloat16(v.y);
    __nv_bfloat16 h2 = __float2bfloat16(v.z);
    __nv_bfloat16 h3 = __float2bfloat16(v.w);
    __nv_bfloat16 l0 = __float2bfloat16(v.x - __bfloat162float(h0));
    __nv_bfloat16 l1 = __float2bfloat16(v.y - __bfloat162float(h1));
    __nv_bfloat16 l2 = __float2bfloat16(v.z - __bfloat162float(h2));
    __nv_bfloat16 l3 = __float2bfloat16(v.w - __bfloat162float(h3));

    uint2 ph, pl;
    ph.x = ((unsigned)__bfloat16_as_ushort(h1) << 16) | __bfloat16_as_ushort(h0);
    ph.y = ((unsigned)__bfloat16_as_ushort(h3) << 16) | __bfloat16_as_ushort(h2);
    pl.x = ((unsigned)__bfloat16_as_ushort(l1) << 16) | __bfloat16_as_ushort(l0);
    pl.y = ((unsigned)__bfloat16_as_ushort(l3) << 16) | __bfloat16_as_ushort(l2);
    ((uint2*)g_Xhi)[(size_t)row * 32 + lane] = ph;
    ((uint2*)g_Xlo)[(size_t)row * 32 + lane] = pl;

    float s = v.x * v.x + v.y * v.y + v.z * v.z + v.w * v.w;
#pragma unroll
    for (int o = 16; o; o >>= 1) s += __shfl_xor_sync(0xffffffffu, s, o);
    if (lane == 0) g_sq[row] = s;
}

// ---------------- ptx helpers ----------------
__device__ __forceinline__ void mma_bf16(float* c, const unsigned* a,
                                         unsigned b0, unsigned b1) {
    asm volatile(
        "mma.sync.aligned.m16n8k16.row.col.f32.bf16.bf16.f32 "
        "{%0,%1,%2,%3}, {%4,%5,%6,%7}, {%8,%9}, {%0,%1,%2,%3};"
        : "+f"(c[0]), "+f"(c[1]), "+f"(c[2]), "+f"(c[3])
        : "r"(a[0]), "r"(a[1]), "r"(a[2]), "r"(a[3]), "r"(b0), "r"(b1));
}
__device__ __forceinline__ void ldsm_x4(unsigned* r, unsigned addr) {
    asm volatile("ldmatrix.sync.aligned.m8n8.x4.shared.b16 {%0,%1,%2,%3}, [%4];"
                 : "=r"(r[0]), "=r"(r[1]), "=r"(r[2]), "=r"(r[3]) : "r"(addr));
}
__device__ __forceinline__ void ldsm_x2(unsigned& r0, unsigned& r1, unsigned addr) {
    asm volatile("ldmatrix.sync.aligned.m8n8.x2.shared.b16 {%0,%1}, [%2];"
                 : "=r"(r0), "=r"(r1) : "r"(addr));
}
__device__ __forceinline__ void cp16(unsigned dst, const void* src) {
    asm volatile("cp.async.cg.shared.global [%0], [%1], 16;" :: "r"(dst), "l"(src));
}
__device__ __forceinline__ void cp_commit() {
    asm volatile("cp.async.commit_group;");
}
__device__ __forceinline__ void cp_wait0() {
    asm volatile("cp.async.wait_group 0;");
}

// ---------------- kernel 3: tensor-core squared-distance matrix -----------
// 128x128 block tile, 8 warps (4x2), warp = 32(M)x64(N). Split-bf16
// (hi.hi + hi.lo + lo.hi, fp32 accum). ldmatrix operand loads, cp.async
// double-buffered K-chunks.
__global__ __launch_bounds__(256, 2) void dist_tc_kernel() {
    extern __shared__ __align__(16) __nv_bfloat16 dsm[];
    unsigned sbase = (unsigned)__cvta_generic_to_shared(dsm);

    int bi = blockIdx.y, bj = blockIdx.x;
    int row0 = bi * 128, col0 = bj * 128;

    int tid  = threadIdx.x;
    int w    = tid >> 5, lane = tid & 31;
    int wm   = w & 3,    wn   = w >> 2;
    int g    = lane >> 2, tig = lane & 3;

    float C[2][8][4];
#pragma unroll
    for (int mt = 0; mt < 2; mt++)
#pragma unroll
        for (int nt = 0; nt < 8; nt++)
#pragma unroll
            for (int q = 0; q < 4; q++) C[mt][nt][q] = 0.f;

    // loader lambda-ish: stage s, chunk kb
    int lr  = tid >> 2;           // 0..63 -> covers rows in 2 passes
    int lc8 = (tid & 3) * 8;      // k offset within chunk (8 bf16 = 16 B)

#pragma unroll 1
    for (int pre = 0; pre < 1; pre++) {   // issue stage 0 loads
#pragma unroll
        for (int u = 0; u < 2; u++) {
            int r = lr + u * 64;
            unsigned db = sbase + (unsigned)((r * TSTR + lc8) * 2);
            size_t goA = (size_t)(row0 + r) * DD + lc8;
            size_t goB = (size_t)(col0 + r) * DD + lc8;
            cp16(db + 0 * TILE * 2, &g_Xhi[goA]);
            cp16(db + 1 * TILE * 2, &g_Xlo[goA]);
            cp16(db + 2 * TILE * 2, &g_Xhi[goB]);
            cp16(db + 3 * TILE * 2, &g_Xlo[goB]);
        }
        cp_commit();
    }

#pragma unroll
    for (int kb = 0; kb < DD / KC; kb++) {
        cp_wait0();
        __syncthreads();

        if (kb < DD / KC - 1) {   // issue next chunk into other stage
            unsigned soff = (unsigned)(((kb + 1) & 1) * STAGE_E * 2);
            int kn = (kb + 1) * KC;
#pragma unroll
            for (int u = 0; u < 2; u++) {
                int r = lr + u * 64;
                unsigned db = sbase + soff + (unsigned)((r * TSTR + lc8) * 2);
                size_t goA = (size_t)(row0 + r) * DD + kn + lc8;
                size_t goB = (size_t)(col0 + r) * DD + kn + lc8;
                cp16(db + 0 * TILE * 2, &g_Xhi[goA]);
                cp16(db + 1 * TILE * 2, &g_Xlo[goA]);
                cp16(db + 2 * TILE * 2, &g_Xhi[goB]);
                cp16(db + 3 * TILE * 2, &g_Xlo[goB]);
            }
            cp_commit();
        }

        unsigned sb = sbase + (unsigned)((kb & 1) * STAGE_E * 2);
#pragma unroll
        for (int ks = 0; ks < KC; ks += 16) {
            unsigned ahi[2][4], alo[2][4];
            int arow = (lane & 15);
            int akc  = ks + (lane >> 4) * 8;
#pragma unroll
            for (int mt = 0; mt < 2; mt++) {
                int row = wm * 32 + mt * 16 + arow;
                unsigned ao = sb + (unsigned)((row * TSTR + akc) * 2);
                ldsm_x4(ahi[mt], ao + 0 * TILE * 2);
                ldsm_x4(alo[mt], ao + 1 * TILE * 2);
            }
            int brow = (lane & 7);
            int bkc  = ks + ((lane >> 3) & 1) * 8;
#pragma unroll
            for (int nt = 0; nt < 8; nt++) {
                int n = wn * 64 + nt * 8 + brow;
                unsigned bo = sb + (unsigned)((n * TSTR + bkc) * 2);
                unsigned bh0, bh1, bl0, bl1;
                ldsm_x2(bh0, bh1, bo + 2 * TILE * 2);
                ldsm_x2(bl0, bl1, bo + 3 * TILE * 2);
#pragma unroll
                for (int mt = 0; mt < 2; mt++) {
                    mma_bf16(C[mt][nt], ahi[mt], bh0, bh1);
                    mma_bf16(C[mt][nt], ahi[mt], bl0, bl1);
                    mma_bf16(C[mt][nt], alo[mt], bh0, bh1);
                }
            }
        }
        __syncthreads();
    }

    // epilogue: d2 = sa + sb - 2*dot, clamped
    float sb0[8], sb1[8];
#pragma unroll
    for (int nt = 0; nt < 8; nt++) {
        int n = col0 + wn * 64 + nt * 8 + tig * 2;
        sb0[nt] = g_sq[n];
        sb1[nt] = g_sq[n + 1];
    }
#pragma unroll
    for (int mt = 0; mt < 2; mt++) {
        int m0 = row0 + wm * 32 + mt * 16;
        float saA = g_sq[m0 + g];
        float saB = g_sq[m0 + g + 8];
#pragma unroll
        for (int nt = 0; nt < 8; nt++) {
            int n = col0 + wn * 64 + nt * 8 + tig * 2;
            float2 oA, oB;
            oA.x = fmaxf(saA + sb0[nt] - 2.f * C[mt][nt][0], 0.f);
            oA.y = fmaxf(saA + sb1[nt] - 2.f * C[mt][nt][1], 0.f);
            oB.x = fmaxf(saB + sb0[nt] - 2.f * C[mt][nt][2], 0.f);
            oB.y = fmaxf(saB + sb1[nt] - 2.f * C[mt][nt][3], 0.f);
            *(float2*)(g_dist + (size_t)(m0 + g) * NN + n)     = oA;
            *(float2*)(g_dist + (size_t)(m0 + g + 8) * NN + n) = oB;
        }
    }
}

// ---------------- kernel 4: per-row top-K, histogram select ---------------
// Per-warp private u16 histograms (match_any leader updates, NO atomics in
// the histogram pass). Pass 2 re-reads the row from L2.
__global__ __launch_bounds__(256) void topk_kernel() {
    int i = blockIdx.x, tid = threadIdx.x;
    int lane = tid & 31, wid = tid >> 5;

    __shared__ unsigned short whist[8][HB];           // 32 KB
    __shared__ unsigned long long bnd[BCAP];          // 2 KB
    __shared__ unsigned long long cand[32];
    __shared__ int wsum[8];
    __shared__ int s_pivot, s_below, n_cand, n_bnd;

    for (int j = tid; j < 8 * HB / 2; j += 256) ((unsigned*)whist)[j] = 0u;
    if (tid == 0) { n_cand = 0; n_bnd = 0; }
    __syncthreads();

    const float4* r4 = (const float4*)(g_dist + (size_t)i * NN);
    unsigned short* mh = whist[wid];

    // pass 1: private per-warp histogram of float bits >> 20
#pragma unroll
    for (int u = 0; u < 8; u++) {
        float4 v = r4[tid + 256 * u];
        float e[4] = {v.x, v.y, v.z, v.w};
#pragma unroll
        for (int q = 0; q < 4; q++) {
            unsigned bin = __float_as_uint(e[q]) >> 20;
            unsigned peers = __match_any_sync(0xffffffffu, bin);
            if (lane == __ffs(peers) - 1)
                mh[bin] = (unsigned short)(mh[bin] + __popc(peers));
        }
    }
    __syncthreads();

    // block prefix scan over per-thread partials (8 bins each, summed
    // across the 8 warp-private histograms) -> pivot bin
    int hsum[8];
    int p = 0;
#pragma unroll
    for (int q = 0; q < 8; q++) {
        int h = 0;
#pragma unroll
        for (int ww = 0; ww < 8; ww++) h += whist[ww][tid * 8 + q];
        hsum[q] = h;
        p += h;
    }
    int v = p;
#pragma unroll
    for (int o = 1; o < 32; o <<= 1) {
        int n = __shfl_up_sync(0xffffffffu, v, o);
        if (lane >= o) v += n;
    }
    if (lane == 31) wsum[wid] = v;
    __syncthreads();
    if (tid < 8) {
        int w = wsum[tid];
#pragma unroll
        for (int o = 1; o < 8; o <<= 1) {
            int n = __shfl_up_sync(0xffu, w, o);
            if (tid >= o) w += n;
        }
        wsum[tid] = w;
    }
    __syncthreads();
    int incl = v + (wid ? wsum[wid - 1] : 0);
    int excl = incl - p;
    if (excl < KNN && incl >= KNN) {
        int c = excl, B = 0;
        for (int q = 0; q < 8; q++) {
            if (c + hsum[q] >= KNN) { B = tid * 8 + q; break; }
            c += hsum[q];
        }
        s_pivot = B;
        s_below = c;
    }
    __syncthreads();

    // pass 2 (L2-hot): collect below-pivot + boundary-bin candidates
    unsigned B = (unsigned)s_pivot;
#pragma unroll
    for (int u = 0; u < 8; u++) {
        int j4 = tid + 256 * u;
        float4 vv = r4[j4];
        float elem[4] = {vv.x, vv.y, vv.z, vv.w};
#pragma unroll
        for (int q = 0; q < 4; q++) {
            unsigned bb = __float_as_uint(elem[q]);
            unsigned bin = bb >> 20;
            if (bin <= B) {
                int j = j4 * 4 + q;
                unsigned long long key =
                    ((unsigned long long)bb << 32) | (unsigned)j;
                if (bin < B) {
                    cand[atomicAdd(&n_cand, 1)] = key;     // guaranteed < 20
                } else {
                    int pos = atomicAdd(&n_bnd, 1);
                    if (pos < BCAP) bnd[pos] = key;
                }
            }
        }
    }
    __syncthreads();

    // warp 0: exact selection from boundary bin + finish row
    if (wid == 0) {
        int below = s_below;
        int need  = KNN - below;
        int nb    = n_bnd;
        if (nb <= BCAP) {
            for (int t = 0; t < need; t++) {
                unsigned long long m = 0xFFFFFFFFFFFFFFFFull;
                for (int j = lane; j < nb; j += 32) {
                    unsigned long long k = bnd[j];
                    if (k < m) m = k;
                }
#pragma unroll
                for (int o = 16; o; o >>= 1) {
                    unsigned long long oth = __shfl_xor_sync(0xffffffffu, m, o);
                    if (oth < m) m = oth;
                }
                for (int j = lane; j < nb; j += 32)
                    if (bnd[j] == m) bnd[j] = 0xFFFFFFFFFFFFFFFFull;
                if (lane == 0) cand[below + t] = m;
            }
        } else {
            const float* row = g_dist + (size_t)i * NN;
            unsigned long long last = 0;
            for (int t = 0; t < need; t++) {
                unsigned long long m = 0xFFFFFFFFFFFFFFFFull;
                for (int j = lane; j < NN; j += 32) {
                    unsigned bb = __float_as_uint(row[j]);
                    if ((bb >> 20) == B) {
                        unsigned long long key =
                            ((unsigned long long)bb << 32) | (unsigned)j;
                        if ((t == 0 || key > last) && key < m) m = key;
                    }
                }
#pragma unroll
                for (int o = 16; o; o >>= 1) {
                    unsigned long long oth = __shfl_xor_sync(0xffffffffu, m, o);
                    if (oth < m) m = oth;
                }
                last = m;
                if (lane == 0) cand[below + t] = m;
            }
        }
        __syncwarp();

        float d = 0.f;
        if (lane < KNN) {
            unsigned long long k = cand[lane];
            int idx = (int)(k & 0xFFFFFFFFull);
            d = sqrtf(__uint_as_float((unsigned)(k >> 32)));
            atomicOr(&g_mask[(size_t)i * NW + (idx >> 5)], 1u << (idx & 31));
            atomicOr(&g_mask[(size_t)idx * NW + (i >> 5)], 1u << (i & 31));
        }
#pragma unroll
        for (int o = 16; o; o >>= 1) d += __shfl_xor_sync(0xffffffffu, d, o);
        if (lane == 0)
            g_density[i] = 1.0f / (d / (float)KNN + 1e-10f);
    }
}

// ---------------- kernel 5: influence average + score + classify ----------
__global__ void final_kernel(const float* __restrict__ logits,
                             float* __restrict__ out, int out_size) {
    int row  = blockIdx.x * 8 + (threadIdx.x >> 5);
    int lane = threadIdx.x & 31;
    const unsigned int* mr = g_mask + (size_t)row * NW;

    float s = 0.f;
    int cnt = 0;
#pragma unroll
    for (int u = 0; u < 8; u++) {
        int w = lane + 32 * u;
        unsigned int bits = mr[w];
        cnt += __popc(bits);
        while (bits) {
            int b = __ffs(bits) - 1;
            bits &= bits - 1;
            s += g_density[w * 32 + b];
        }
    }
#pragma unroll
    for (int o = 16; o; o >>= 1) {
        s   += __shfl_xor_sync(0xffffffffu, s, o);
        cnt += __shfl_xor_sync(0xffffffffu, cnt, o);
    }
    if (lane == 0) {
        float den   = g_density[row];
        float avg   = s / (float)(cnt > 0 ? cnt : 1);
        float score = -(den / (avg + 1e-10f));
        out[row] = score;
        bool flag = score < -0.5f;
        if (out_size >= 2 * NN) out[NN + row] = flag ? 1.f : 0.f;
        if (out_size >= 3 * NN) {
            int pred = -1;
            if (!flag) {
                const float* lg = logits + (size_t)row * NC;
                float best = lg[0]; pred = 0;
#pragma unroll
                for (int c = 1; c < NC; c++)
                    if (lg[c] > best) { best = lg[c]; pred = c; }
            }
            out[2 * NN + row] = (float)pred;
        }
    }
}

// ---------------- launch ----------------
extern "C" void kernel_launch(void* const* d_in, const int* in_sizes, int n_in,
                              void* d_out, int out_size) {
    (void)in_sizes; (void)n_in;
    const float* X = (const float*)d_in[0];   // embeddings [8192,128] f32
    const float* L = (const float*)d_in[1];   // logits     [8192,10]  f32
    float* out = (float*)d_out;

    static int smem_set = 0;
    if (!smem_set) {
        cudaFuncSetAttribute(dist_tc_kernel,
                             cudaFuncAttributeMaxDynamicSharedMemorySize,
                             DIST_SMEM);
        smem_set = 1;
    }

    zero_mask_kernel<<<(NN * NW + 255) / 256, 256>>>();
    prep_kernel<<<NN / 8, 256>>>(X);
    dim3 g(NN / 128, NN / 128);
    dist_tc_kernel<<<g, 256, DIST_SMEM>>>();
    topk_kernel<<<NN, 256>>>();
    final_kernel<<<NN / 8, 256>>>(L, out, out_size);
}